// round 13
// baseline (speedup 1.0000x reference)
#include <cuda_runtime.h>
#include <cuda_fp16.h>
#include <math.h>
#include <stdint.h>

#define DD 7686
#define HH 512
#define OO 8
#define NN 8206
#define MM 2048
#define KP 7712        // padded K pitch in elements (241 * 32)
#define NKH 241        // K-tiles of 32 halfs
#define NPAD 7808      // padded N rows for B operand (61 * 128)

// ---------------------------------------------------------------------------
// Scratch (device globals)
// ---------------------------------------------------------------------------
__device__ __align__(1024) uint16_t g_Xh [MM * KP];      // X   fp16 [2048, KP]
__device__ __align__(1024) uint16_t g_Wth[NPAD * KP];    // W^T fp16 (Wq then Wk)
__device__ __align__(1024) uint16_t g_Qh [MM * KP];      // Q   fp16
__device__ __align__(1024) uint16_t g_Kh [MM * KP];      // K   fp16
__device__ __align__(1024) float    g_S  [MM * MM];
__device__ __align__(256) float g_rmax[MM], g_rscale[MM];
__device__ __align__(256) float g_partW[8 * MM], g_w[MM];
__device__ __align__(256) float g_partU[8 * DD], g_u[DD];
__device__ __align__(256) float g_partC[16 * DD], g_ctx[DD];
__device__ __align__(256) float g_partH[64 * 520], g_h[520];

// ---------------------------------------------------------------------------
// cp.async
// ---------------------------------------------------------------------------
__device__ __forceinline__ void cp16(unsigned d, const void* s) {
    asm volatile("cp.async.cg.shared.global [%0], [%1], 16;" :: "r"(d), "l"(s));
}
#define CP_COMMIT() asm volatile("cp.async.commit_group;" ::)

// m16n8k16 fp16 MMA, fp16 accumulate (2 f16x2 accumulator regs)
__device__ __forceinline__ void mma16h(unsigned c[2], const unsigned a[4], const unsigned b[2]) {
    asm volatile(
        "mma.sync.aligned.m16n8k16.row.col.f16.f16.f16.f16 "
        "{%0,%1}, {%2,%3,%4,%5}, {%6,%7}, {%0,%1};\n"
        : "+r"(c[0]), "+r"(c[1])
        : "r"(a[0]), "r"(a[1]), "r"(a[2]), "r"(a[3]), "r"(b[0]), "r"(b[1]));
}

// ---------------------------------------------------------------------------
// fp16 GEMM: C[2048, Nn] = A[2048, KP] * B[rows, KP]^T   (both K-contiguous,
// zero-padded to KP: no K guards). Block 128x128, K-tile 32, 8 warps
// (warp tile 64x32). 4-stage cp.async pipeline, one __syncthreads per iter.
// fp16 accumulate with fp32 promotion every 32 k-tiles (split-K precision).
// WH=1: fp16 C with bias (pads zeroed). WH=0: fp32 C * scale.
// ---------------------------------------------------------------------------
#define ST   40                       // smem row stride in halfs (80B, conflict-free)
#define ELE  (128 * ST)               // halfs per operand per stage (10240B)
#define SMEM_H (4 * 2 * ELE * 2)      // 81920 bytes dynamic smem

template <int WH>
__global__ void __launch_bounds__(256, 1)
gemm_h(const uint16_t* __restrict__ A, const uint16_t* __restrict__ B,
       float* __restrict__ Cf, uint16_t* __restrict__ Ch,
       const float* __restrict__ bias, float scale, int Nn, int Cpitch)
{
    extern __shared__ __align__(128) uint16_t sm[];
    uint16_t* As = sm;                 // 4 stages x ELE
    uint16_t* Bs = sm + 4 * ELE;       // 4 stages x ELE

    const int t    = threadIdx.x;
    const int warp = t >> 5, lane = t & 31;
    const int grp  = lane >> 2, tig = lane & 3;
    const int wm   = warp & 1, wn = warp >> 1;
    const int bM   = blockIdx.x, bN = blockIdx.y;

    const unsigned sA = (unsigned)__cvta_generic_to_shared(As);
    const unsigned sB = (unsigned)__cvta_generic_to_shared(Bs);

    unsigned hacc[4][4][2];            // fp16x2 running accumulators
    float    macc[4][4][4];            // fp32 masters
#pragma unroll
    for (int i = 0; i < 4; i++)
#pragma unroll
        for (int j = 0; j < 4; j++) {
            hacc[i][j][0] = 0u; hacc[i][j][1] = 0u;
#pragma unroll
            for (int k = 0; k < 4; k++) macc[i][j][k] = 0.f;
        }

    auto loadTile = [&](int kt) {
        const int buf = kt & 3, k0 = kt << 5;
#pragma unroll
        for (int i = 0; i < 2; i++) {                 // A: 512 chunks of 8 halfs
            int c = t + 256 * i;
            int row = c >> 2, kc = (c & 3) << 3;
            cp16(sA + (unsigned)(buf * ELE + row * ST + kc) * 2u,
                 A + (size_t)(bM * 128 + row) * KP + k0 + kc);
        }
#pragma unroll
        for (int i = 0; i < 2; i++) {                 // B: 512 chunks
            int c = t + 256 * i;
            int row = c >> 2, kc = (c & 3) << 3;
            cp16(sB + (unsigned)(buf * ELE + row * ST + kc) * 2u,
                 B + (size_t)(bN * 128 + row) * KP + k0 + kc);
        }
    };

    auto promote = [&]() {
#pragma unroll
        for (int im = 0; im < 4; im++)
#pragma unroll
            for (int jn = 0; jn < 4; jn++) {
                __half2 p0 = *reinterpret_cast<__half2*>(&hacc[im][jn][0]);
                __half2 p1 = *reinterpret_cast<__half2*>(&hacc[im][jn][1]);
                float2 f0 = __half22float2(p0);
                float2 f1 = __half22float2(p1);
                macc[im][jn][0] += f0.x; macc[im][jn][1] += f0.y;
                macc[im][jn][2] += f1.x; macc[im][jn][3] += f1.y;
                hacc[im][jn][0] = 0u; hacc[im][jn][1] = 0u;
            }
    };

    loadTile(0); CP_COMMIT();
    loadTile(1); CP_COMMIT();
    loadTile(2); CP_COMMIT();

    for (int kt = 0; kt < NKH; kt++) {
        if (kt < NKH - 2)      asm volatile("cp.async.wait_group 2;" ::);
        else if (kt < NKH - 1) asm volatile("cp.async.wait_group 1;" ::);
        else                   asm volatile("cp.async.wait_group 0;" ::);
        __syncthreads();   // tile kt visible to all; compute(kt-1) done by all

        if (kt + 3 < NKH) { loadTile(kt + 3); CP_COMMIT(); }

        const uint16_t* Ab = As + (kt & 3) * ELE;
        const uint16_t* Bb = Bs + (kt & 3) * ELE;

#pragma unroll
        for (int s = 0; s < 2; s++) {                 // two k16 steps per k32 tile
            const int kb = s << 4;
            unsigned a[4][4], b[4][2];
#pragma unroll
            for (int im = 0; im < 4; im++) {
                int r = wm * 64 + im * 16 + grp;
                a[im][0] = *(const unsigned*)&Ab[r * ST + kb + 2 * tig];
                a[im][1] = *(const unsigned*)&Ab[(r + 8) * ST + kb + 2 * tig];
                a[im][2] = *(const unsigned*)&Ab[r * ST + kb + 2 * tig + 8];
                a[im][3] = *(const unsigned*)&Ab[(r + 8) * ST + kb + 2 * tig + 8];
            }
#pragma unroll
            for (int jn = 0; jn < 4; jn++) {
                int cc = wn * 32 + jn * 8 + grp;
                b[jn][0] = *(const unsigned*)&Bb[cc * ST + kb + 2 * tig];
                b[jn][1] = *(const unsigned*)&Bb[cc * ST + kb + 2 * tig + 8];
            }
#pragma unroll
            for (int im = 0; im < 4; im++)
#pragma unroll
                for (int jn = 0; jn < 4; jn++)
                    mma16h(hacc[im][jn], a[im], b[jn]);
        }

        // split-K: promote fp16 accumulators to fp32 every 32 k-tiles
        if (((kt & 31) == 31) || (kt == NKH - 1)) promote();
    }

    // ---- epilogue ----
#pragma unroll
    for (int im = 0; im < 4; im++) {
#pragma unroll
        for (int jn = 0; jn < 4; jn++) {
            int r  = bM * 128 + wm * 64 + im * 16 + grp;
            int cc = bN * 128 + wn * 32 + jn * 8 + (tig << 1);
#pragma unroll
            for (int e = 0; e < 2; e++) {
                int n = cc + e;
                float v0 = macc[im][jn][0 + e];   // row r
                float v1 = macc[im][jn][2 + e];   // row r+8
                if (WH) {
                    if (n < Nn) {
                        float bb = bias[n];
                        Ch[(size_t)r * Cpitch + n] =
                            __half_as_ushort(__float2half_rn(v0 + bb));
                        Ch[(size_t)(r + 8) * Cpitch + n] =
                            __half_as_ushort(__float2half_rn(v1 + bb));
                    } else if (n < Cpitch) {     // zero the K-pad columns
                        Ch[(size_t)r * Cpitch + n] = 0;
                        Ch[(size_t)(r + 8) * Cpitch + n] = 0;
                    }
                } else {
                    if (n < Nn) {
                        Cf[(size_t)r * Cpitch + n] = v0 * scale;
                        Cf[(size_t)(r + 8) * Cpitch + n] = v1 * scale;
                    }
                }
            }
        }
    }
}

// ---- X fp32 -> fp16 padded ----
__global__ void conv_x(const float* __restrict__ X, uint16_t* __restrict__ Xh)
{
    const int j = blockIdx.x * 256 + threadIdx.x;
    const int m = blockIdx.y;
    if (j >= KP) return;
    float v = (j < DD) ? X[(size_t)m * DD + j] : 0.f;
    Xh[(size_t)m * KP + j] = __half_as_ushort(__float2half_rn(v));
}

// ---- W fp32 [k][n] -> W^T fp16 [n][KP] padded (rows to NPAD) ----
__global__ void convT_w(const float* __restrict__ W, uint16_t* __restrict__ Wt)
{
    __shared__ float tile[32][33];
    const int kx = blockIdx.x * 32, ny = blockIdx.y * 32;
    const int tx = threadIdx.x, ty = threadIdx.y;
#pragma unroll
    for (int i = 0; i < 4; i++) {
        int k = kx + ty + i * 8, n = ny + tx;
        tile[ty + i * 8][tx] = (k < DD && n < DD) ? W[(size_t)k * DD + n] : 0.f;
    }
    __syncthreads();
#pragma unroll
    for (int i = 0; i < 4; i++) {
        int n = ny + ty + i * 8, k = kx + tx;
        if (n < NPAD)
            Wt[(size_t)n * KP + k] = __half_as_ushort(__float2half_rn(tile[tx][ty + i * 8]));
    }
}

// ---- softmax / reductions / graph sweeps (unchanged, passing) ----
__global__ void row_softmax_stats(const float* __restrict__ S, float* __restrict__ rmax,
                                  float* __restrict__ rscale)
{
    __shared__ float red[256];
    const int m = blockIdx.x, t = threadIdx.x;
    const float* row = S + (size_t)m * MM;
    float mx = -3.402823e38f;
    for (int j = t; j < MM; j += 256) mx = fmaxf(mx, row[j]);
    red[t] = mx; __syncthreads();
    for (int s = 128; s > 0; s >>= 1) { if (t < s) red[t] = fmaxf(red[t], red[t + s]); __syncthreads(); }
    mx = red[0]; __syncthreads();
    float sm = 0.f;
    for (int j = t; j < MM; j += 256) sm += __expf(row[j] - mx);
    red[t] = sm; __syncthreads();
    for (int s = 128; s > 0; s >>= 1) { if (t < s) red[t] += red[t + s]; __syncthreads(); }
    if (t == 0) { rmax[m] = mx; rscale[m] = 1.f / (red[0] * (float)MM); }
}
__global__ void colmean_partial(const float* __restrict__ S, const float* __restrict__ rmax,
                                const float* __restrict__ rscale, float* __restrict__ part)
{
    const int j = blockIdx.x * 256 + threadIdx.x, mb = blockIdx.y, m0 = mb * 256;
    float acc = 0.f;
#pragma unroll 4
    for (int m = m0; m < m0 + 256; m++)
        acc += __expf(S[(size_t)m * MM + j] - rmax[m]) * rscale[m];
    part[mb * MM + j] = acc;
}
__global__ void reduce_w(const float* __restrict__ part, float* __restrict__ w)
{
    const int j = blockIdx.x * 256 + threadIdx.x;
    float s = 0.f;
#pragma unroll
    for (int c = 0; c < 8; c++) s += part[c * MM + j];
    w[j] = s;
}
__global__ void wx_partial(const float* __restrict__ X, const float* __restrict__ w,
                           float* __restrict__ part)
{
    const int d = blockIdx.x * 256 + threadIdx.x, mb = blockIdx.y;
    if (d >= DD) return;
    const int m0 = mb * 256;
    float acc = 0.f;
#pragma unroll 4
    for (int m = m0; m < m0 + 256; m++) acc += w[m] * X[(size_t)m * DD + d];
    part[mb * DD + d] = acc;
}
__global__ void reduce_u(const float* __restrict__ part, float* __restrict__ u)
{
    const int d = blockIdx.x * 256 + threadIdx.x;
    if (d >= DD) return;
    float s = 0.f;
#pragma unroll
    for (int c = 0; c < 8; c++) s += part[c * DD + d];
    u[d] = s;
}
__global__ void uwv_partial(const float* __restrict__ u, const float* __restrict__ Wv,
                            float* __restrict__ part)
{
    const int n = blockIdx.x * 256 + threadIdx.x, kb = blockIdx.y;
    if (n >= DD) return;
    const int k0 = kb * 481, k1 = (k0 + 481 < DD) ? (k0 + 481) : DD;
    float acc = 0.f;
    for (int k = k0; k < k1; k++) acc += u[k] * Wv[(size_t)k * DD + n];
    part[kb * DD + n] = acc;
}
__global__ void reduce_ctx(const float* __restrict__ part, const float* __restrict__ bv,
                           float* __restrict__ ctx)
{
    const int n = blockIdx.x * 256 + threadIdx.x;
    if (n >= DD) return;
    float s = 0.f;
#pragma unroll
    for (int c = 0; c < 16; c++) s += part[c * DD + n];
    ctx[n] = s + bv[n];
}
__global__ void sweep1_partial(const float* __restrict__ ctx, const float* __restrict__ mu,
                               const float* __restrict__ sg, const float* __restrict__ ep,
                               float* __restrict__ part)
{
    const int j = blockIdx.x * 256 + threadIdx.x, ib = blockIdx.y;
    if (j >= HH + OO) return;
    const int i0 = ib * 121, i1 = (i0 + 121 < DD) ? (i0 + 121) : DD;
    float acc = 0.f;
    for (int i = i0; i < i1; i++) {
        size_t off = (size_t)i * NN + DD + j;
        acc += ctx[i] * (mu[off] + sg[off] * ep[off]);
    }
    part[ib * (HH + OO) + j] = acc;
}
__global__ void reduce_h(const float* __restrict__ part, const float* __restrict__ bmu,
                         const float* __restrict__ bsg, const float* __restrict__ epb,
                         float* __restrict__ h)
{
    const int j = blockIdx.x * 256 + threadIdx.x;
    if (j >= HH + OO) return;
    float s = 0.f;
#pragma unroll
    for (int c = 0; c < 64; c++) s += part[c * (HH + OO) + j];
    s += bmu[DD + j] + bsg[DD + j] * epb[DD + j];
    h[j] = tanhf(s);
}
__global__ void sweep2_out(const float* __restrict__ ctx, const float* __restrict__ h,
                           const float* __restrict__ mu, const float* __restrict__ sg,
                           const float* __restrict__ ep, const float* __restrict__ bmu,
                           const float* __restrict__ bsg, const float* __restrict__ epb,
                           float* __restrict__ out)
{
    __shared__ float red[8][256];
    const int t = threadIdx.x;
    float acc[8];
#pragma unroll
    for (int o = 0; o < 8; o++) acc[o] = 0.f;
    for (int i = t; i < NN; i += 256) {
        float zi = (i < DD) ? ctx[i] : h[i - DD];
        size_t base = (size_t)i * NN + (DD + HH);
#pragma unroll
        for (int o = 0; o < 8; o++) acc[o] += zi * (mu[base + o] + sg[base + o] * ep[base + o]);
    }
#pragma unroll
    for (int o = 0; o < 8; o++) red[o][t] = acc[o];
    __syncthreads();
    for (int s = 128; s > 0; s >>= 1) {
        if (t < s)
#pragma unroll
            for (int o = 0; o < 8; o++) red[o][t] += red[o][t + s];
        __syncthreads();
    }
    if (t < 8) {
        float b2 = bmu[DD + HH + t] + bsg[DD + HH + t] * epb[DD + HH + t];
        out[t] = 1.f / (1.f + expf(-tanhf(red[t][0] + b2)));
    }
}

// ---------------------------------------------------------------------------
extern "C" void kernel_launch(void* const* d_in, const int* in_sizes, int n_in,
                              void* d_out, int out_size)
{
    const float* X   = (const float*)d_in[0];
    const float* Wq  = (const float*)d_in[1];
    const float* bq  = (const float*)d_in[2];
    const float* Wk  = (const float*)d_in[3];
    const float* bk  = (const float*)d_in[4];
    const float* Wv  = (const float*)d_in[5];
    const float* bv  = (const float*)d_in[6];
    const float* mu  = (const float*)d_in[7];
    const float* sg  = (const float*)d_in[8];
    const float* bmu = (const float*)d_in[9];
    const float* bsg = (const float*)d_in[10];
    const float* epw = (const float*)d_in[11];
    const float* epb = (const float*)d_in[12];
    float* out = (float*)d_out;

    uint16_t *Xh, *Wth, *Qh, *Kh;
    float *S, *rmax, *rscale, *partW, *w, *partU, *u, *partC, *ctx, *partH, *h;
    cudaGetSymbolAddress((void**)&Xh,  g_Xh);
    cudaGetSymbolAddress((void**)&Wth, g_Wth);
    cudaGetSymbolAddress((void**)&Qh,  g_Qh);
    cudaGetSymbolAddress((void**)&Kh,  g_Kh);
    cudaGetSymbolAddress((void**)&S,   g_S);
    cudaGetSymbolAddress((void**)&rmax, g_rmax);
    cudaGetSymbolAddress((void**)&rscale, g_rscale);
    cudaGetSymbolAddress((void**)&partW, g_partW);
    cudaGetSymbolAddress((void**)&w, g_w);
    cudaGetSymbolAddress((void**)&partU, g_partU);
    cudaGetSymbolAddress((void**)&u, g_u);
    cudaGetSymbolAddress((void**)&partC, g_partC);
    cudaGetSymbolAddress((void**)&ctx, g_ctx);
    cudaGetSymbolAddress((void**)&partH, g_partH);
    cudaGetSymbolAddress((void**)&h, g_h);

    cudaFuncSetAttribute(gemm_h<1>, cudaFuncAttributeMaxDynamicSharedMemorySize, SMEM_H);
    cudaFuncSetAttribute(gemm_h<0>, cudaFuncAttributeMaxDynamicSharedMemorySize, SMEM_H);

    const float inv_sqrt_d = 1.0f / sqrtf((float)DD);
    const dim3 tb32(32, 8);
    const dim3 tgw(KP / 32, NPAD / 32);

    // fp16 conversions
    conv_x<<<dim3((KP + 255) / 256, MM), 256>>>(X, Xh);

    // Q = X Wq + bq   (fp16 out, pads zeroed)
    convT_w<<<tgw, tb32>>>(Wq, Wth);
    gemm_h<1><<<dim3(16, 61), 256, SMEM_H>>>(Xh, Wth, nullptr, Qh, bq, 1.0f, DD, KP);
    // K = X Wk + bk
    convT_w<<<tgw, tb32>>>(Wk, Wth);
    gemm_h<1><<<dim3(16, 61), 256, SMEM_H>>>(Xh, Wth, nullptr, Kh, bk, 1.0f, DD, KP);
    // S = Q K^T / sqrt(D)   (fp32 out)
    gemm_h<0><<<dim3(16, 16), 256, SMEM_H>>>(Qh, Kh, S, nullptr, nullptr, inv_sqrt_d, MM, MM);

    row_softmax_stats<<<MM, 256>>>(S, rmax, rscale);
    colmean_partial<<<dim3(8, 8), 256>>>(S, rmax, rscale, partW);
    reduce_w<<<8, 256>>>(partW, w);
    wx_partial<<<dim3(31, 8), 256>>>(X, w, partU);
    reduce_u<<<31, 256>>>(partU, u);
    uwv_partial<<<dim3(31, 16), 256>>>(u, Wv, partC);
    reduce_ctx<<<31, 256>>>(partC, bv, ctx);
    sweep1_partial<<<dim3(3, 64), 256>>>(ctx, mu, sg, epw, partH);
    reduce_h<<<3, 256>>>(partH, bmu, bsg, epb, h);
    sweep2_out<<<1, 256>>>(ctx, h, mu, sg, epw, bmu, bsg, epb, out);
}

// round 14
// speedup vs baseline: 1.3452x; 1.3452x over previous
#include <cuda_runtime.h>
#include <cuda_fp16.h>
#include <math.h>
#include <stdint.h>

#define DD 7686
#define HH 512
#define OO 8
#define NN 8206
#define MM 2048
#define KP 7712        // padded K pitch in elements (241 * 32)
#define NKH 241        // K-tiles of 32 halfs
#define NPAD 7808      // padded N rows per operand half (61 * 128)

// ---------------------------------------------------------------------------
// Scratch (device globals)
// ---------------------------------------------------------------------------
__device__ __align__(1024) uint16_t g_Xh [MM * KP];          // X fp16 [2048, KP]
__device__ __align__(1024) uint16_t g_Wqk[2 * NPAD * KP];    // [Wq^T ; Wk^T] fp16
__device__ __align__(1024) uint16_t g_Qh [MM * KP];          // Q fp16
__device__ __align__(1024) uint16_t g_Kh [MM * KP];          // K fp16
__device__ __align__(1024) float    g_S  [MM * MM];
__device__ __align__(256) float g_rmax[MM], g_rscale[MM];
__device__ __align__(256) float g_partW[8 * MM], g_w[MM];
__device__ __align__(256) float g_partU[8 * DD], g_u[DD];
__device__ __align__(256) float g_partC[16 * DD], g_ctx[DD];
__device__ __align__(256) float g_partH[64 * 520], g_h[520];

// ---------------------------------------------------------------------------
// cp.async
// ---------------------------------------------------------------------------
__device__ __forceinline__ void cp16(unsigned d, const void* s) {
    asm volatile("cp.async.cg.shared.global [%0], [%1], 16;" :: "r"(d), "l"(s));
}
#define CP_COMMIT() asm volatile("cp.async.commit_group;" ::)

// m16n8k16 fp16 MMA, fp32 accumulate
__device__ __forceinline__ void mma16(float c[4], const unsigned a[4], const unsigned b[2]) {
    asm volatile(
        "mma.sync.aligned.m16n8k16.row.col.f32.f16.f16.f32 "
        "{%0,%1,%2,%3}, {%4,%5,%6,%7}, {%8,%9}, {%0,%1,%2,%3};\n"
        : "+f"(c[0]), "+f"(c[1]), "+f"(c[2]), "+f"(c[3])
        : "r"(a[0]), "r"(a[1]), "r"(a[2]), "r"(a[3]), "r"(b[0]), "r"(b[1]));
}

#define ST   40                       // smem row stride in halfs (80B, conflict-free)
#define ELE  (128 * ST)               // halfs per operand per stage (10240B)
#define SMEM_H (4 * 2 * ELE * 2)      // 81920 bytes dynamic smem

// ---------------------------------------------------------------------------
// Shared mainloop macro-body via device function: computes 128x128 fp32 acc
// tile of A[2048,KP] * B[rows,KP]^T, 4-stage cp.async, one sync per iter.
// ---------------------------------------------------------------------------
struct MainloopOut { float acc[4][4][4]; };

__device__ __forceinline__ void gemm_mainloop(
    const uint16_t* __restrict__ A, const uint16_t* __restrict__ B,
    int bM, int bN, int t, float acc[4][4][4])
{
    extern __shared__ __align__(128) uint16_t sm[];
    uint16_t* As = sm;
    uint16_t* Bs = sm + 4 * ELE;

    const int warp = t >> 5, lane = t & 31;
    const int grp  = lane >> 2, tig = lane & 3;
    const int wm   = warp & 1, wn = warp >> 1;

    const unsigned sA = (unsigned)__cvta_generic_to_shared(As);
    const unsigned sB = (unsigned)__cvta_generic_to_shared(Bs);

#pragma unroll
    for (int i = 0; i < 4; i++)
#pragma unroll
        for (int j = 0; j < 4; j++)
#pragma unroll
            for (int k = 0; k < 4; k++) acc[i][j][k] = 0.f;

    auto loadTile = [&](int kt) {
        const int buf = kt & 3, k0 = kt << 5;
#pragma unroll
        for (int i = 0; i < 2; i++) {
            int c = t + 256 * i;
            int row = c >> 2, kc = (c & 3) << 3;
            cp16(sA + (unsigned)(buf * ELE + row * ST + kc) * 2u,
                 A + (size_t)(bM * 128 + row) * KP + k0 + kc);
        }
#pragma unroll
        for (int i = 0; i < 2; i++) {
            int c = t + 256 * i;
            int row = c >> 2, kc = (c & 3) << 3;
            cp16(sB + (unsigned)(buf * ELE + row * ST + kc) * 2u,
                 B + (size_t)(bN * 128 + row) * KP + k0 + kc);
        }
    };

    loadTile(0); CP_COMMIT();
    loadTile(1); CP_COMMIT();
    loadTile(2); CP_COMMIT();

    for (int kt = 0; kt < NKH; kt++) {
        if (kt < NKH - 2)      asm volatile("cp.async.wait_group 2;" ::);
        else if (kt < NKH - 1) asm volatile("cp.async.wait_group 1;" ::);
        else                   asm volatile("cp.async.wait_group 0;" ::);
        __syncthreads();

        if (kt + 3 < NKH) { loadTile(kt + 3); CP_COMMIT(); }

        const uint16_t* Ab = As + (kt & 3) * ELE;
        const uint16_t* Bb = Bs + (kt & 3) * ELE;

#pragma unroll
        for (int s = 0; s < 2; s++) {
            const int kb = s << 4;
            unsigned a[4][4], b[4][2];
#pragma unroll
            for (int im = 0; im < 4; im++) {
                int r = wm * 64 + im * 16 + grp;
                a[im][0] = *(const unsigned*)&Ab[r * ST + kb + 2 * tig];
                a[im][1] = *(const unsigned*)&Ab[(r + 8) * ST + kb + 2 * tig];
                a[im][2] = *(const unsigned*)&Ab[r * ST + kb + 2 * tig + 8];
                a[im][3] = *(const unsigned*)&Ab[(r + 8) * ST + kb + 2 * tig + 8];
            }
#pragma unroll
            for (int jn = 0; jn < 4; jn++) {
                int cc = wn * 32 + jn * 8 + grp;
                b[jn][0] = *(const unsigned*)&Bb[cc * ST + kb + 2 * tig];
                b[jn][1] = *(const unsigned*)&Bb[cc * ST + kb + 2 * tig + 8];
            }
#pragma unroll
            for (int im = 0; im < 4; im++)
#pragma unroll
                for (int jn = 0; jn < 4; jn++)
                    mma16(acc[im][jn], a[im], b[jn]);
        }
    }
}

// ---------------------------------------------------------------------------
// Fused Q+K GEMM: one launch over B = [Wq^T ; Wk^T] (2*NPAD rows).
// bN < 61 -> Q half (+bq), bN >= 61 -> K half (+bk). fp16 out, pads zeroed.
// ---------------------------------------------------------------------------
__global__ void __launch_bounds__(256, 2)
gemm_qk(const uint16_t* __restrict__ A, const uint16_t* __restrict__ B,
        uint16_t* __restrict__ Qo, uint16_t* __restrict__ Ko,
        const float* __restrict__ bq, const float* __restrict__ bk)
{
    const int t  = threadIdx.x;
    const int bM = blockIdx.x, bN = blockIdx.y;
    float acc[4][4][4];
    gemm_mainloop(A, B, bM, bN, t, acc);

    const int warp = t >> 5, lane = t & 31;
    const int grp  = lane >> 2, tig = lane & 3;
    const int wm   = warp & 1, wn = warp >> 1;

    const int half = (bN >= 61);
    uint16_t* Co = half ? Ko : Qo;
    const float* bi = half ? bk : bq;
    const int nbase = bN * 128 - half * NPAD;

#pragma unroll
    for (int im = 0; im < 4; im++) {
#pragma unroll
        for (int jn = 0; jn < 4; jn++) {
            int r  = bM * 128 + wm * 64 + im * 16 + grp;
            int cc = nbase + wn * 32 + jn * 8 + (tig << 1);
#pragma unroll
            for (int e = 0; e < 2; e++) {
                int n = cc + e;
                float v0 = acc[im][jn][0 + e];
                float v1 = acc[im][jn][2 + e];
                if (n < DD) {
                    float bb = bi[n];
                    Co[(size_t)r * KP + n]       = __half_as_ushort(__float2half_rn(v0 + bb));
                    Co[(size_t)(r + 8) * KP + n] = __half_as_ushort(__float2half_rn(v1 + bb));
                } else if (n < KP) {
                    Co[(size_t)r * KP + n] = 0;
                    Co[(size_t)(r + 8) * KP + n] = 0;
                }
            }
        }
    }
}

// ---------------------------------------------------------------------------
// S GEMM: S[2048,2048] = Q K^T * scale (fp32 out)
// ---------------------------------------------------------------------------
__global__ void __launch_bounds__(256, 2)
gemm_s(const uint16_t* __restrict__ A, const uint16_t* __restrict__ B,
       float* __restrict__ C, float scale)
{
    const int t  = threadIdx.x;
    const int bM = blockIdx.x, bN = blockIdx.y;
    float acc[4][4][4];
    gemm_mainloop(A, B, bM, bN, t, acc);

    const int warp = t >> 5, lane = t & 31;
    const int grp  = lane >> 2, tig = lane & 3;
    const int wm   = warp & 1, wn = warp >> 1;

#pragma unroll
    for (int im = 0; im < 4; im++) {
#pragma unroll
        for (int jn = 0; jn < 4; jn++) {
            int r  = bM * 128 + wm * 64 + im * 16 + grp;
            int cc = bN * 128 + wn * 32 + jn * 8 + (tig << 1);
#pragma unroll
            for (int e = 0; e < 2; e++) {
                int n = cc + e;
                C[(size_t)r * MM + n]       = acc[im][jn][0 + e] * scale;
                C[(size_t)(r + 8) * MM + n] = acc[im][jn][2 + e] * scale;
            }
        }
    }
}

// ---- X fp32 -> fp16 padded (float2/half2 vectorized; rows 8B aligned) ----
__global__ void conv_x(const float* __restrict__ X, uint16_t* __restrict__ Xh)
{
    const int j2 = blockIdx.x * 256 + threadIdx.x;   // pair index
    const int m  = blockIdx.y;
    const int j  = j2 * 2;
    if (j >= KP) return;
    __half2 h;
    if (j + 1 < DD) {
        float2 v = *(const float2*)(X + (size_t)m * DD + j);
        h = __floats2half2_rn(v.x, v.y);
    } else {
        h = __floats2half2_rn(0.f, 0.f);
    }
    *(__half2*)(Xh + (size_t)m * KP + j) = h;
}

// ---- W fp32 [k][n] -> W^T fp16 [n][KP]; 64-wide K tiles, half2 stores ----
__global__ void convT_w(const float* __restrict__ W, uint16_t* __restrict__ Wt)
{
    __shared__ float tile[64][33];
    const int kx = blockIdx.x * 64, ny = blockIdx.y * 32;
    const int tx = threadIdx.x, ty = threadIdx.y;     // 32 x 8
#pragma unroll
    for (int i = 0; i < 8; i++) {
        int k = kx + ty + i * 8, n = ny + tx;
        tile[ty + i * 8][tx] = (k < DD && n < DD) ? W[(size_t)k * DD + n] : 0.f;
    }
    __syncthreads();
#pragma unroll
    for (int i = 0; i < 4; i++) {
        int n = ny + ty + i * 8;
        int k = kx + 2 * tx;
        if (k < KP) {
            __half2 h = __floats2half2_rn(tile[2 * tx][ty + i * 8],
                                          tile[2 * tx + 1][ty + i * 8]);
            *(__half2*)(Wt + (size_t)n * KP + k) = h;
        }
    }
}

// ---- softmax / reductions / graph sweeps (unchanged, passing) ----
__global__ void row_softmax_stats(const float* __restrict__ S, float* __restrict__ rmax,
                                  float* __restrict__ rscale)
{
    __shared__ float red[256];
    const int m = blockIdx.x, t = threadIdx.x;
    const float* row = S + (size_t)m * MM;
    float mx = -3.402823e38f;
    for (int j = t; j < MM; j += 256) mx = fmaxf(mx, row[j]);
    red[t] = mx; __syncthreads();
    for (int s = 128; s > 0; s >>= 1) { if (t < s) red[t] = fmaxf(red[t], red[t + s]); __syncthreads(); }
    mx = red[0]; __syncthreads();
    float sm = 0.f;
    for (int j = t; j < MM; j += 256) sm += __expf(row[j] - mx);
    red[t] = sm; __syncthreads();
    for (int s = 128; s > 0; s >>= 1) { if (t < s) red[t] += red[t + s]; __syncthreads(); }
    if (t == 0) { rmax[m] = mx; rscale[m] = 1.f / (red[0] * (float)MM); }
}
__global__ void colmean_partial(const float* __restrict__ S, const float* __restrict__ rmax,
                                const float* __restrict__ rscale, float* __restrict__ part)
{
    const int j = blockIdx.x * 256 + threadIdx.x, mb = blockIdx.y, m0 = mb * 256;
    float acc = 0.f;
#pragma unroll 4
    for (int m = m0; m < m0 + 256; m++)
        acc += __expf(S[(size_t)m * MM + j] - rmax[m]) * rscale[m];
    part[mb * MM + j] = acc;
}
__global__ void reduce_w(const float* __restrict__ part, float* __restrict__ w)
{
    const int j = blockIdx.x * 256 + threadIdx.x;
    float s = 0.f;
#pragma unroll
    for (int c = 0; c < 8; c++) s += part[c * MM + j];
    w[j] = s;
}
__global__ void wx_partial(const float* __restrict__ X, const float* __restrict__ w,
                           float* __restrict__ part)
{
    const int d = blockIdx.x * 256 + threadIdx.x, mb = blockIdx.y;
    if (d >= DD) return;
    const int m0 = mb * 256;
    float acc = 0.f;
#pragma unroll 4
    for (int m = m0; m < m0 + 256; m++) acc += w[m] * X[(size_t)m * DD + d];
    part[mb * DD + d] = acc;
}
__global__ void reduce_u(const float* __restrict__ part, float* __restrict__ u)
{
    const int d = blockIdx.x * 256 + threadIdx.x;
    if (d >= DD) return;
    float s = 0.f;
#pragma unroll
    for (int c = 0; c < 8; c++) s += part[c * DD + d];
    u[d] = s;
}
__global__ void uwv_partial(const float* __restrict__ u, const float* __restrict__ Wv,
                            float* __restrict__ part)
{
    const int n = blockIdx.x * 256 + threadIdx.x, kb = blockIdx.y;
    if (n >= DD) return;
    const int k0 = kb * 481, k1 = (k0 + 481 < DD) ? (k0 + 481) : DD;
    float acc = 0.f;
    for (int k = k0; k < k1; k++) acc += u[k] * Wv[(size_t)k * DD + n];
    part[kb * DD + n] = acc;
}
__global__ void reduce_ctx(const float* __restrict__ part, const float* __restrict__ bv,
                           float* __restrict__ ctx)
{
    const int n = blockIdx.x * 256 + threadIdx.x;
    if (n >= DD) return;
    float s = 0.f;
#pragma unroll
    for (int c = 0; c < 16; c++) s += part[c * DD + n];
    ctx[n] = s + bv[n];
}
__global__ void sweep1_partial(const float* __restrict__ ctx, const float* __restrict__ mu,
                               const float* __restrict__ sg, const float* __restrict__ ep,
                               float* __restrict__ part)
{
    const int j = blockIdx.x * 256 + threadIdx.x, ib = blockIdx.y;
    if (j >= HH + OO) return;
    const int i0 = ib * 121, i1 = (i0 + 121 < DD) ? (i0 + 121) : DD;
    float acc = 0.f;
    for (int i = i0; i < i1; i++) {
        size_t off = (size_t)i * NN + DD + j;
        acc += ctx[i] * (mu[off] + sg[off] * ep[off]);
    }
    part[ib * (HH + OO) + j] = acc;
}
__global__ void reduce_h(const float* __restrict__ part, const float* __restrict__ bmu,
                         const float* __restrict__ bsg, const float* __restrict__ epb,
                         float* __restrict__ h)
{
    const int j = blockIdx.x * 256 + threadIdx.x;
    if (j >= HH + OO) return;
    float s = 0.f;
#pragma unroll
    for (int c = 0; c < 64; c++) s += part[c * (HH + OO) + j];
    s += bmu[DD + j] + bsg[DD + j] * epb[DD + j];
    h[j] = tanhf(s);
}
__global__ void sweep2_out(const float* __restrict__ ctx, const float* __restrict__ h,
                           const float* __restrict__ mu, const float* __restrict__ sg,
                           const float* __restrict__ ep, const float* __restrict__ bmu,
                           const float* __restrict__ bsg, const float* __restrict__ epb,
                           float* __restrict__ out)
{
    __shared__ float red[8][256];
    const int t = threadIdx.x;
    float acc[8];
#pragma unroll
    for (int o = 0; o < 8; o++) acc[o] = 0.f;
    for (int i = t; i < NN; i += 256) {
        float zi = (i < DD) ? ctx[i] : h[i - DD];
        size_t base = (size_t)i * NN + (DD + HH);
#pragma unroll
        for (int o = 0; o < 8; o++) acc[o] += zi * (mu[base + o] + sg[base + o] * ep[base + o]);
    }
#pragma unroll
    for (int o = 0; o < 8; o++) red[o][t] = acc[o];
    __syncthreads();
    for (int s = 128; s > 0; s >>= 1) {
        if (t < s)
#pragma unroll
            for (int o = 0; o < 8; o++) red[o][t] += red[o][t + s];
        __syncthreads();
    }
    if (t < 8) {
        float b2 = bmu[DD + HH + t] + bsg[DD + HH + t] * epb[DD + HH + t];
        out[t] = 1.f / (1.f + expf(-tanhf(red[t][0] + b2)));
    }
}

// ---------------------------------------------------------------------------
extern "C" void kernel_launch(void* const* d_in, const int* in_sizes, int n_in,
                              void* d_out, int out_size)
{
    const float* X   = (const float*)d_in[0];
    const float* Wq  = (const float*)d_in[1];
    const float* bq  = (const float*)d_in[2];
    const float* Wk  = (const float*)d_in[3];
    const float* bk  = (const float*)d_in[4];
    const float* Wv  = (const float*)d_in[5];
    const float* bv  = (const float*)d_in[6];
    const float* mu  = (const float*)d_in[7];
    const float* sg  = (const float*)d_in[8];
    const float* bmu = (const float*)d_in[9];
    const float* bsg = (const float*)d_in[10];
    const float* epw = (const float*)d_in[11];
    const float* epb = (const float*)d_in[12];
    float* out = (float*)d_out;

    uint16_t *Xh, *Wqk, *Qh, *Kh;
    float *S, *rmax, *rscale, *partW, *w, *partU, *u, *partC, *ctx, *partH, *h;
    cudaGetSymbolAddress((void**)&Xh,  g_Xh);
    cudaGetSymbolAddress((void**)&Wqk, g_Wqk);
    cudaGetSymbolAddress((void**)&Qh,  g_Qh);
    cudaGetSymbolAddress((void**)&Kh,  g_Kh);
    cudaGetSymbolAddress((void**)&S,   g_S);
    cudaGetSymbolAddress((void**)&rmax, g_rmax);
    cudaGetSymbolAddress((void**)&rscale, g_rscale);
    cudaGetSymbolAddress((void**)&partW, g_partW);
    cudaGetSymbolAddress((void**)&w, g_w);
    cudaGetSymbolAddress((void**)&partU, g_partU);
    cudaGetSymbolAddress((void**)&u, g_u);
    cudaGetSymbolAddress((void**)&partC, g_partC);
    cudaGetSymbolAddress((void**)&ctx, g_ctx);
    cudaGetSymbolAddress((void**)&partH, g_partH);
    cudaGetSymbolAddress((void**)&h, g_h);

    cudaFuncSetAttribute(gemm_qk, cudaFuncAttributeMaxDynamicSharedMemorySize, SMEM_H);
    cudaFuncSetAttribute(gemm_s,  cudaFuncAttributeMaxDynamicSharedMemorySize, SMEM_H);

    const float inv_sqrt_d = 1.0f / sqrtf((float)DD);
    const dim3 tb32(32, 8);
    const dim3 tgw((KP + 63) / 64, NPAD / 32);    // 121 x 244

    // conversions
    conv_x<<<dim3((KP / 2 + 255) / 256, MM), 256>>>(X, Xh);
    convT_w<<<tgw, tb32>>>(Wq, Wqk);
    convT_w<<<tgw, tb32>>>(Wk, Wqk + (size_t)NPAD * KP);

    // fused Q & K GEMM (one launch, one tail)
    gemm_qk<<<dim3(16, 122), 256, SMEM_H>>>(Xh, Wqk, Qh, Kh, bq, bk);

    // S = Q K^T / sqrt(D)
    gemm_s<<<dim3(16, 16), 256, SMEM_H>>>(Qh, Kh, S, inv_sqrt_d);

    row_softmax_stats<<<MM, 256>>>(S, rmax, rscale);
    colmean_partial<<<dim3(8, 8), 256>>>(S, rmax, rscale, partW);
    reduce_w<<<8, 256>>>(partW, w);
    wx_partial<<<dim3(31, 8), 256>>>(X, w, partU);
    reduce_u<<<31, 256>>>(partU, u);
    uwv_partial<<<dim3(31, 16), 256>>>(u, Wv, partC);
    reduce_ctx<<<31, 256>>>(partC, bv, ctx);
    sweep1_partial<<<dim3(3, 64), 256>>>(ctx, mu, sg, epw, partH);
    reduce_h<<<3, 256>>>(partH, bmu, bsg, epb, h);
    sweep2_out<<<1, 256>>>(ctx, h, mu, sg, epw, bmu, bsg, epb, out);
}

// round 15
// speedup vs baseline: 1.3723x; 1.0202x over previous
#include <cuda_runtime.h>
#include <cuda_fp16.h>
#include <math.h>
#include <stdint.h>

#define DD 7686
#define HH 512
#define OO 8
#define NN 8206
#define MM 2048
#define KP 7712        // padded K pitch in elements (241 * 32)
#define NKH 241        // K-tiles of 32 halfs
#define NPAD 7808      // padded N rows per operand half (61 * 128)

// ---------------------------------------------------------------------------
// Scratch (device globals)
// ---------------------------------------------------------------------------
__device__ __align__(1024) uint16_t g_Xh [MM * KP];          // X fp16 [2048, KP]
__device__ __align__(1024) uint16_t g_Wqk[2 * NPAD * KP];    // [Wq^T ; Wk^T] fp16
__device__ __align__(1024) uint16_t g_P  [4 * MM * KP];      // split-K partials {Q0,Q1,K0,K1}
__device__ __align__(1024) uint16_t g_Qh [MM * KP];          // Q fp16
__device__ __align__(1024) uint16_t g_Kh [MM * KP];          // K fp16
__device__ __align__(1024) float    g_S  [MM * MM];
__device__ __align__(256) float g_rmax[MM], g_rscale[MM];
__device__ __align__(256) float g_partW[16 * MM], g_w[MM];
__device__ __align__(256) float g_partU[8 * DD], g_u[DD];
__device__ __align__(256) float g_partC[16 * DD], g_ctx[DD];
__device__ __align__(256) float g_partH[64 * 520], g_h[520];

// ---------------------------------------------------------------------------
// cp.async
// ---------------------------------------------------------------------------
__device__ __forceinline__ void cp16(unsigned d, const void* s) {
    asm volatile("cp.async.cg.shared.global [%0], [%1], 16;" :: "r"(d), "l"(s));
}
#define CP_COMMIT() asm volatile("cp.async.commit_group;" ::)

// m16n8k16 fp16 MMA, fp32 accumulate
__device__ __forceinline__ void mma16(float c[4], const unsigned a[4], const unsigned b[2]) {
    asm volatile(
        "mma.sync.aligned.m16n8k16.row.col.f32.f16.f16.f32 "
        "{%0,%1,%2,%3}, {%4,%5,%6,%7}, {%8,%9}, {%0,%1,%2,%3};\n"
        : "+f"(c[0]), "+f"(c[1]), "+f"(c[2]), "+f"(c[3])
        : "r"(a[0]), "r"(a[1]), "r"(a[2]), "r"(a[3]), "r"(b[0]), "r"(b[1]));
}
// m16n8k16 fp16 MMA, fp16 accumulate
__device__ __forceinline__ void mma16h(unsigned c[2], const unsigned a[4], const unsigned b[2]) {
    asm volatile(
        "mma.sync.aligned.m16n8k16.row.col.f16.f16.f16.f16 "
        "{%0,%1}, {%2,%3,%4,%5}, {%6,%7}, {%0,%1};\n"
        : "+r"(c[0]), "+r"(c[1])
        : "r"(a[0]), "r"(a[1]), "r"(a[2]), "r"(a[3]), "r"(b[0]), "r"(b[1]));
}

#define ST   40                       // smem row stride in halfs (80B, conflict-free)
#define ELE  (128 * ST)               // halfs per operand per stage (10240B)
#define SMEM_H (4 * 2 * ELE * 2)      // 81920 bytes dynamic smem

// ---------------------------------------------------------------------------
// Tile loader shared by both GEMMs
// ---------------------------------------------------------------------------
__device__ __forceinline__ void load_tile(
    const uint16_t* __restrict__ A, const uint16_t* __restrict__ B,
    unsigned sA, unsigned sB, int bM, int bN, int t, int kt)
{
    const int buf = kt & 3, k0 = kt << 5;
#pragma unroll
    for (int i = 0; i < 2; i++) {
        int c = t + 256 * i;
        int row = c >> 2, kc = (c & 3) << 3;
        cp16(sA + (unsigned)(buf * ELE + row * ST + kc) * 2u,
             A + (size_t)(bM * 128 + row) * KP + k0 + kc);
    }
#pragma unroll
    for (int i = 0; i < 2; i++) {
        int c = t + 256 * i;
        int row = c >> 2, kc = (c & 3) << 3;
        cp16(sB + (unsigned)(buf * ELE + row * ST + kc) * 2u,
             B + (size_t)(bN * 128 + row) * KP + k0 + kc);
    }
}

// ---------------------------------------------------------------------------
// Fused Q+K GEMM, f16 accumulate, split-K=2 (blockIdx.z), fp16 partials out.
// ---------------------------------------------------------------------------
__global__ void __launch_bounds__(256, 2)
gemm_qk16(const uint16_t* __restrict__ A, const uint16_t* __restrict__ B,
          uint16_t* __restrict__ P)
{
    extern __shared__ __align__(128) uint16_t sm[];
    uint16_t* As = sm;
    uint16_t* Bs = sm + 4 * ELE;

    const int t    = threadIdx.x;
    const int warp = t >> 5, lane = t & 31;
    const int grp  = lane >> 2, tig = lane & 3;
    const int wm   = warp & 1, wn = warp >> 1;
    const int bM   = blockIdx.x, bN = blockIdx.y, kz = blockIdx.z;

    const int ks = kz ? 121 : 0;
    const int ke = kz ? NKH : 121;

    const unsigned sA = (unsigned)__cvta_generic_to_shared(As);
    const unsigned sB = (unsigned)__cvta_generic_to_shared(Bs);

    unsigned hacc[4][4][2];
#pragma unroll
    for (int i = 0; i < 4; i++)
#pragma unroll
        for (int j = 0; j < 4; j++) { hacc[i][j][0] = 0u; hacc[i][j][1] = 0u; }

    load_tile(A, B, sA, sB, bM, bN, t, ks);     CP_COMMIT();
    load_tile(A, B, sA, sB, bM, bN, t, ks + 1); CP_COMMIT();
    load_tile(A, B, sA, sB, bM, bN, t, ks + 2); CP_COMMIT();

    for (int kt = ks; kt < ke; kt++) {
        const int rem = ke - 1 - kt;
        if (rem >= 2)      asm volatile("cp.async.wait_group 2;" ::);
        else if (rem == 1) asm volatile("cp.async.wait_group 1;" ::);
        else               asm volatile("cp.async.wait_group 0;" ::);
        __syncthreads();

        if (kt + 3 < ke) { load_tile(A, B, sA, sB, bM, bN, t, kt + 3); CP_COMMIT(); }

        const uint16_t* Ab = As + (kt & 3) * ELE;
        const uint16_t* Bb = Bs + (kt & 3) * ELE;

#pragma unroll
        for (int s = 0; s < 2; s++) {
            const int kb = s << 4;
            unsigned a[4][4], b[4][2];
#pragma unroll
            for (int im = 0; im < 4; im++) {
                int r = wm * 64 + im * 16 + grp;
                a[im][0] = *(const unsigned*)&Ab[r * ST + kb + 2 * tig];
                a[im][1] = *(const unsigned*)&Ab[(r + 8) * ST + kb + 2 * tig];
                a[im][2] = *(const unsigned*)&Ab[r * ST + kb + 2 * tig + 8];
                a[im][3] = *(const unsigned*)&Ab[(r + 8) * ST + kb + 2 * tig + 8];
            }
#pragma unroll
            for (int jn = 0; jn < 4; jn++) {
                int cc = wn * 32 + jn * 8 + grp;
                b[jn][0] = *(const unsigned*)&Bb[cc * ST + kb + 2 * tig];
                b[jn][1] = *(const unsigned*)&Bb[cc * ST + kb + 2 * tig + 8];
            }
#pragma unroll
            for (int im = 0; im < 4; im++)
#pragma unroll
                for (int jn = 0; jn < 4; jn++)
                    mma16h(hacc[im][jn], a[im], b[jn]);
        }
    }

    // ---- epilogue: fp16x2 partials to gmem ----
    const int half = (bN >= 61);
    uint16_t* Pd = P + ((size_t)(half * 2 + kz)) * MM * KP;
    const int nbase = bN * 128 - half * NPAD;

#pragma unroll
    for (int im = 0; im < 4; im++) {
#pragma unroll
        for (int jn = 0; jn < 4; jn++) {
            int r  = bM * 128 + wm * 64 + im * 16 + grp;
            int cc = nbase + wn * 32 + jn * 8 + (tig << 1);
            if (cc < KP) {
                *(unsigned*)&Pd[(size_t)r * KP + cc]       = hacc[im][jn][0];
                *(unsigned*)&Pd[(size_t)(r + 8) * KP + cc] = hacc[im][jn][1];
            }
        }
    }
}

// ---- combine split-K partials + bias -> Q/K fp16 (pads zeroed) ----
__global__ void combine_qk(const uint16_t* __restrict__ P,
                           const float* __restrict__ bq, const float* __restrict__ bk,
                           uint16_t* __restrict__ Qh, uint16_t* __restrict__ Kh)
{
    const int p = blockIdx.x * 256 + threadIdx.x;
    const int total = MM * (KP / 2);
    if (p >= total) return;
    const int m = p / (KP / 2);
    const int j = (p - m * (KP / 2)) * 2;
    const size_t off = (size_t)m * KP + j;

    if (j < DD) {
        float2 b0 = *(const float2*)(bq + j);
        float2 b1 = *(const float2*)(bk + j);
        float2 q0 = __half22float2(*(const __half2*)&P[0 * (size_t)MM * KP + off]);
        float2 q1 = __half22float2(*(const __half2*)&P[1 * (size_t)MM * KP + off]);
        float2 k0 = __half22float2(*(const __half2*)&P[2 * (size_t)MM * KP + off]);
        float2 k1 = __half22float2(*(const __half2*)&P[3 * (size_t)MM * KP + off]);
        *(__half2*)&Qh[off] = __floats2half2_rn(q0.x + q1.x + b0.x, q0.y + q1.y + b0.y);
        *(__half2*)&Kh[off] = __floats2half2_rn(k0.x + k1.x + b1.x, k0.y + k1.y + b1.y);
    } else {
        *(__half2*)&Qh[off] = __floats2half2_rn(0.f, 0.f);
        *(__half2*)&Kh[off] = __floats2half2_rn(0.f, 0.f);
    }
}

// ---------------------------------------------------------------------------
// S GEMM: S[2048,2048] = Q K^T * scale (f32 accumulate, fp32 out)
// ---------------------------------------------------------------------------
__global__ void __launch_bounds__(256, 2)
gemm_s(const uint16_t* __restrict__ A, const uint16_t* __restrict__ B,
       float* __restrict__ C, float scale)
{
    extern __shared__ __align__(128) uint16_t sm[];
    uint16_t* As = sm;
    uint16_t* Bs = sm + 4 * ELE;

    const int t    = threadIdx.x;
    const int warp = t >> 5, lane = t & 31;
    const int grp  = lane >> 2, tig = lane & 3;
    const int wm   = warp & 1, wn = warp >> 1;
    const int bM   = blockIdx.x, bN = blockIdx.y;

    const unsigned sA = (unsigned)__cvta_generic_to_shared(As);
    const unsigned sB = (unsigned)__cvta_generic_to_shared(Bs);

    float acc[4][4][4];
#pragma unroll
    for (int i = 0; i < 4; i++)
#pragma unroll
        for (int j = 0; j < 4; j++)
#pragma unroll
            for (int k = 0; k < 4; k++) acc[i][j][k] = 0.f;

    load_tile(A, B, sA, sB, bM, bN, t, 0); CP_COMMIT();
    load_tile(A, B, sA, sB, bM, bN, t, 1); CP_COMMIT();
    load_tile(A, B, sA, sB, bM, bN, t, 2); CP_COMMIT();

    for (int kt = 0; kt < NKH; kt++) {
        if (kt < NKH - 2)      asm volatile("cp.async.wait_group 2;" ::);
        else if (kt < NKH - 1) asm volatile("cp.async.wait_group 1;" ::);
        else                   asm volatile("cp.async.wait_group 0;" ::);
        __syncthreads();

        if (kt + 3 < NKH) { load_tile(A, B, sA, sB, bM, bN, t, kt + 3); CP_COMMIT(); }

        const uint16_t* Ab = As + (kt & 3) * ELE;
        const uint16_t* Bb = Bs + (kt & 3) * ELE;

#pragma unroll
        for (int s = 0; s < 2; s++) {
            const int kb = s << 4;
            unsigned a[4][4], b[4][2];
#pragma unroll
            for (int im = 0; im < 4; im++) {
                int r = wm * 64 + im * 16 + grp;
                a[im][0] = *(const unsigned*)&Ab[r * ST + kb + 2 * tig];
                a[im][1] = *(const unsigned*)&Ab[(r + 8) * ST + kb + 2 * tig];
                a[im][2] = *(const unsigned*)&Ab[r * ST + kb + 2 * tig + 8];
                a[im][3] = *(const unsigned*)&Ab[(r + 8) * ST + kb + 2 * tig + 8];
            }
#pragma unroll
            for (int jn = 0; jn < 4; jn++) {
                int cc = wn * 32 + jn * 8 + grp;
                b[jn][0] = *(const unsigned*)&Bb[cc * ST + kb + 2 * tig];
                b[jn][1] = *(const unsigned*)&Bb[cc * ST + kb + 2 * tig + 8];
            }
#pragma unroll
            for (int im = 0; im < 4; im++)
#pragma unroll
                for (int jn = 0; jn < 4; jn++)
                    mma16(acc[im][jn], a[im], b[jn]);
        }
    }

#pragma unroll
    for (int im = 0; im < 4; im++) {
#pragma unroll
        for (int jn = 0; jn < 4; jn++) {
            int r  = bM * 128 + wm * 64 + im * 16 + grp;
            int cc = bN * 128 + wn * 32 + jn * 8 + (tig << 1);
#pragma unroll
            for (int e = 0; e < 2; e++) {
                int n = cc + e;
                C[(size_t)r * MM + n]       = acc[im][jn][0 + e] * scale;
                C[(size_t)(r + 8) * MM + n] = acc[im][jn][2 + e] * scale;
            }
        }
    }
}

// ---- X fp32 -> fp16 padded (float2/half2 vectorized) ----
__global__ void conv_x(const float* __restrict__ X, uint16_t* __restrict__ Xh)
{
    const int j2 = blockIdx.x * 256 + threadIdx.x;
    const int m  = blockIdx.y;
    const int j  = j2 * 2;
    if (j >= KP) return;
    __half2 h;
    if (j + 1 < DD) {
        float2 v = *(const float2*)(X + (size_t)m * DD + j);
        h = __floats2half2_rn(v.x, v.y);
    } else {
        h = __floats2half2_rn(0.f, 0.f);
    }
    *(__half2*)(Xh + (size_t)m * KP + j) = h;
}

// ---- W fp32 [k][n] -> W^T fp16 [n][KP]; 64-wide K tiles, half2 stores ----
__global__ void convT_w(const float* __restrict__ W, uint16_t* __restrict__ Wt)
{
    __shared__ float tile[64][33];
    const int kx = blockIdx.x * 64, ny = blockIdx.y * 32;
    const int tx = threadIdx.x, ty = threadIdx.y;     // 32 x 8
#pragma unroll
    for (int i = 0; i < 8; i++) {
        int k = kx + ty + i * 8, n = ny + tx;
        tile[ty + i * 8][tx] = (k < DD && n < DD) ? W[(size_t)k * DD + n] : 0.f;
    }
    __syncthreads();
#pragma unroll
    for (int i = 0; i < 4; i++) {
        int n = ny + ty + i * 8;
        int k = kx + 2 * tx;
        if (k < KP) {
            __half2 h = __floats2half2_rn(tile[2 * tx][ty + i * 8],
                                          tile[2 * tx + 1][ty + i * 8]);
            *(__half2*)(Wt + (size_t)n * KP + k) = h;
        }
    }
}

// ---- softmax / reductions / graph sweeps ----
__global__ void row_softmax_stats(const float* __restrict__ S, float* __restrict__ rmax,
                                  float* __restrict__ rscale)
{
    __shared__ float red[256];
    const int m = blockIdx.x, t = threadIdx.x;
    const float* row = S + (size_t)m * MM;
    float mx = -3.402823e38f;
    for (int j = t; j < MM; j += 256) mx = fmaxf(mx, row[j]);
    red[t] = mx; __syncthreads();
    for (int s = 128; s > 0; s >>= 1) { if (t < s) red[t] = fmaxf(red[t], red[t + s]); __syncthreads(); }
    mx = red[0]; __syncthreads();
    float sm = 0.f;
    for (int j = t; j < MM; j += 256) sm += __expf(row[j] - mx);
    red[t] = sm; __syncthreads();
    for (int s = 128; s > 0; s >>= 1) { if (t < s) red[t] += red[t + s]; __syncthreads(); }
    if (t == 0) { rmax[m] = mx; rscale[m] = 1.f / (red[0] * (float)MM); }
}
__global__ void colmean_partial(const float* __restrict__ S, const float* __restrict__ rmax,
                                const float* __restrict__ rscale, float* __restrict__ part)
{
    const int j = blockIdx.x * 256 + threadIdx.x, mb = blockIdx.y, m0 = mb * 128;
    float acc = 0.f;
#pragma unroll 4
    for (int m = m0; m < m0 + 128; m++)
        acc += __expf(S[(size_t)m * MM + j] - rmax[m]) * rscale[m];
    part[mb * MM + j] = acc;
}
__global__ void reduce_w(const float* __restrict__ part, float* __restrict__ w)
{
    const int j = blockIdx.x * 256 + threadIdx.x;
    float s = 0.f;
#pragma unroll
    for (int c = 0; c < 16; c++) s += part[c * MM + j];
    w[j] = s;
}
__global__ void wx_partial(const float* __restrict__ X, const float* __restrict__ w,
                           float* __restrict__ part)
{
    const int d = blockIdx.x * 256 + threadIdx.x, mb = blockIdx.y;
    if (d >= DD) return;
    const int m0 = mb * 256;
    float acc = 0.f;
#pragma unroll 4
    for (int m = m0; m < m0 + 256; m++) acc += w[m] * X[(size_t)m * DD + d];
    part[mb * DD + d] = acc;
}
__global__ void reduce_u(const float* __restrict__ part, float* __restrict__ u)
{
    const int d = blockIdx.x * 256 + threadIdx.x;
    if (d >= DD) return;
    float s = 0.f;
#pragma unroll
    for (int c = 0; c < 8; c++) s += part[c * DD + d];
    u[d] = s;
}
__global__ void uwv_partial(const float* __restrict__ u, const float* __restrict__ Wv,
                            float* __restrict__ part)
{
    const int n = blockIdx.x * 256 + threadIdx.x, kb = blockIdx.y;
    if (n >= DD) return;
    const int k0 = kb * 481, k1 = (k0 + 481 < DD) ? (k0 + 481) : DD;
    float acc = 0.f;
    for (int k = k0; k < k1; k++) acc += u[k] * Wv[(size_t)k * DD + n];
    part[kb * DD + n] = acc;
}
__global__ void reduce_ctx(const float* __restrict__ part, const float* __restrict__ bv,
                           float* __restrict__ ctx)
{
    const int n = blockIdx.x * 256 + threadIdx.x;
    if (n >= DD) return;
    float s = 0.f;
#pragma unroll
    for (int c = 0; c < 16; c++) s += part[c * DD + n];
    ctx[n] = s + bv[n];
}
__global__ void sweep1_partial(const float* __restrict__ ctx, const float* __restrict__ mu,
                               const float* __restrict__ sg, const float* __restrict__ ep,
                               float* __restrict__ part)
{
    const int j = blockIdx.x * 256 + threadIdx.x, ib = blockIdx.y;
    if (j >= HH + OO) return;
    const int i0 = ib * 121, i1 = (i0 + 121 < DD) ? (i0 + 121) : DD;
    float acc = 0.f;
    for (int i = i0; i < i1; i++) {
        size_t off = (size_t)i * NN + DD + j;
        acc += ctx[i] * (mu[off] + sg[off] * ep[off]);
    }
    part[ib * (HH + OO) + j] = acc;
}
__global__ void reduce_h(const float* __restrict__ part, const float* __restrict__ bmu,
                         const float* __restrict__ bsg, const float* __restrict__ epb,
                         float* __restrict__ h)
{
    const int j = blockIdx.x * 256 + threadIdx.x;
    if (j >= HH + OO) return;
    float s = 0.f;
#pragma unroll
    for (int c = 0; c < 64; c++) s += part[c * (HH + OO) + j];
    s += bmu[DD + j] + bsg[DD + j] * epb[DD + j];
    h[j] = tanhf(s);
}
__global__ void sweep2_out(const float* __restrict__ ctx, const float* __restrict__ h,
                           const float* __restrict__ mu, const float* __restrict__ sg,
                           const float* __restrict__ ep, const float* __restrict__ bmu,
                           const float* __restrict__ bsg, const float* __restrict__ epb,
                           float* __restrict__ out)
{
    __shared__ float red[8][256];
    const int t = threadIdx.x;
    float acc[8];
#pragma unroll
    for (int o = 0; o < 8; o++) acc[o] = 0.f;
    for (int i = t; i < NN; i += 256) {
        float zi = (i < DD) ? ctx[i] : h[i - DD];
        size_t base = (size_t)i * NN + (DD + HH);
#pragma unroll
        for (int o = 0; o < 8; o++) acc[o] += zi * (mu[base + o] + sg[base + o] * ep[base + o]);
    }
#pragma unroll
    for (int o = 0; o < 8; o++) red[o][t] = acc[o];
    __syncthreads();
    for (int s = 128; s > 0; s >>= 1) {
        if (t < s)
#pragma unroll
            for (int o = 0; o < 8; o++) red[o][t] += red[o][t + s];
        __syncthreads();
    }
    if (t < 8) {
        float b2 = bmu[DD + HH + t] + bsg[DD + HH + t] * epb[DD + HH + t];
        out[t] = 1.f / (1.f + expf(-tanhf(red[t][0] + b2)));
    }
}

// ---------------------------------------------------------------------------
extern "C" void kernel_launch(void* const* d_in, const int* in_sizes, int n_in,
                              void* d_out, int out_size)
{
    const float* X   = (const float*)d_in[0];
    const float* Wq  = (const float*)d_in[1];
    const float* bq  = (const float*)d_in[2];
    const float* Wk  = (const float*)d_in[3];
    const float* bk  = (const float*)d_in[4];
    const float* Wv  = (const float*)d_in[5];
    const float* bv  = (const float*)d_in[6];
    const float* mu  = (const float*)d_in[7];
    const float* sg  = (const float*)d_in[8];
    const float* bmu = (const float*)d_in[9];
    const float* bsg = (const float*)d_in[10];
    const float* epw = (const float*)d_in[11];
    const float* epb = (const float*)d_in[12];
    float* out = (float*)d_out;

    uint16_t *Xh, *Wqk, *P, *Qh, *Kh;
    float *S, *rmax, *rscale, *partW, *w, *partU, *u, *partC, *ctx, *partH, *h;
    cudaGetSymbolAddress((void**)&Xh,  g_Xh);
    cudaGetSymbolAddress((void**)&Wqk, g_Wqk);
    cudaGetSymbolAddress((void**)&P,   g_P);
    cudaGetSymbolAddress((void**)&Qh,  g_Qh);
    cudaGetSymbolAddress((void**)&Kh,  g_Kh);
    cudaGetSymbolAddress((void**)&S,   g_S);
    cudaGetSymbolAddress((void**)&rmax, g_rmax);
    cudaGetSymbolAddress((void**)&rscale, g_rscale);
    cudaGetSymbolAddress((void**)&partW, g_partW);
    cudaGetSymbolAddress((void**)&w, g_w);
    cudaGetSymbolAddress((void**)&partU, g_partU);
    cudaGetSymbolAddress((void**)&u, g_u);
    cudaGetSymbolAddress((void**)&partC, g_partC);
    cudaGetSymbolAddress((void**)&ctx, g_ctx);
    cudaGetSymbolAddress((void**)&partH, g_partH);
    cudaGetSymbolAddress((void**)&h, g_h);

    cudaFuncSetAttribute(gemm_qk16, cudaFuncAttributeMaxDynamicSharedMemorySize, SMEM_H);
    cudaFuncSetAttribute(gemm_s,    cudaFuncAttributeMaxDynamicSharedMemorySize, SMEM_H);

    const float inv_sqrt_d = 1.0f / sqrtf((float)DD);
    const dim3 tb32(32, 8);
    const dim3 tgw((KP + 63) / 64, NPAD / 32);

    // conversions
    conv_x<<<dim3((KP / 2 + 255) / 256, MM), 256>>>(X, Xh);
    convT_w<<<tgw, tb32>>>(Wq, Wqk);
    convT_w<<<tgw, tb32>>>(Wk, Wqk + (size_t)NPAD * KP);

    // fused Q & K GEMM, f16 accumulate, split-K=2
    gemm_qk16<<<dim3(16, 122, 2), 256, SMEM_H>>>(Xh, Wqk, P);
    combine_qk<<<(MM * (KP / 2) + 255) / 256, 256>>>(P, bq, bk, Qh, Kh);

    // S = Q K^T / sqrt(D)  (f32 accumulate)
    gemm_s<<<dim3(16, 16), 256, SMEM_H>>>(Qh, Kh, S, inv_sqrt_d);

    row_softmax_stats<<<MM, 256>>>(S, rmax, rscale);
    colmean_partial<<<dim3(8, 16), 256>>>(S, rmax, rscale, partW);
    reduce_w<<<8, 256>>>(partW, w);
    wx_partial<<<dim3(31, 8), 256>>>(X, w, partU);
    reduce_u<<<31, 256>>>(partU, u);
    uwv_partial<<<dim3(31, 16), 256>>>(u, Wv, partC);
    reduce_ctx<<<31, 256>>>(partC, bv, ctx);
    sweep1_partial<<<dim3(3, 64), 256>>>(ctx, mu, sg, epw, partH);
    reduce_h<<<3, 256>>>(partH, bmu, bsg, epb, h);
    sweep2_out<<<1, 256>>>(ctx, h, mu, sg, epw, bmu, bsg, epb, out);
}